// round 14
// baseline (speedup 1.0000x reference)
#include <cuda_runtime.h>

#define DIM   768
#define POOL  20
#define TOPK  9
#define NVEC  6                 // float4 chunks per lane: 768 / 4 / 32
#define WARPS 8
#define ROWS_PER_WARP  2
#define ROWS_PER_BLOCK (WARPS * ROWS_PER_WARP)   // 16

// Allocation-free scratch
__device__ float        g_kn[POOL * DIM];
__device__ float        g_rowsum[POOL];
__device__ unsigned int g_count[POOL];

// ---------------------------------------------------------------------------
// prep: 1 block x 640 threads. Warp w normalizes key row w (shuffle-only).
// Re-zeros accumulators every replay (graph determinism).
// ---------------------------------------------------------------------------
__global__ void prep_kernel(const float* __restrict__ keys,
                            const int*   __restrict__ layer)
{
    const int w    = threadIdx.x >> 5;
    const int lane = threadIdx.x & 31;

    if (w < POOL) {
        const float* __restrict__ krow =
            keys + ((size_t)(*layer) * POOL + w) * DIM;
        float ss = 0.f;
        #pragma unroll
        for (int i = 0; i < DIM / 32; i++) {
            float v = __ldg(krow + lane + 32 * i);
            ss += v * v;
        }
        #pragma unroll
        for (int off = 16; off; off >>= 1)
            ss += __shfl_xor_sync(0xffffffffu, ss, off);
        const float inv = 1.f / fmaxf(sqrtf(ss), 1e-12f);
        #pragma unroll
        for (int i = 0; i < DIM / 32; i++)
            g_kn[w * DIM + lane + 32 * i] = __ldg(krow + lane + 32 * i) * inv;
    }
    if (threadIdx.x < POOL) {
        g_count[threadIdx.x]  = 0u;
        g_rowsum[threadIdx.x] = 0.f;
    }
}

// ---------------------------------------------------------------------------
// main: one warp handles TWO batch rows; register cap for 4 CTAs/SM
// (32 warps/SM). Same math as the R12 winner.
// ---------------------------------------------------------------------------
__global__ void __launch_bounds__(256, 4)
pool_main(const float* __restrict__ x,
          const float* __restrict__ prompts,
          const int*   __restrict__ layer,
          float*       __restrict__ out,
          int B)
{
    __shared__ unsigned int s_count[POOL];
    if (threadIdx.x < POOL) s_count[threadIdx.x] = 0u;
    __syncthreads();

    const int warp = threadIdx.x >> 5;
    const int lane = threadIdx.x & 31;
    const int r0   = blockIdx.x * ROWS_PER_BLOCK + warp * ROWS_PER_WARP;
    const int r1   = r0 + 1;

    if (r1 < B) {
        const float4* __restrict__ xr0 = (const float4*)(x + (size_t)r0 * DIM);
        const float4* __restrict__ xr1 = (const float4*)(x + (size_t)r1 * DIM);
        const float4* __restrict__ knv = (const float4*)g_kn;

        float s0[POOL], s1[POOL];
        #pragma unroll
        for (int j = 0; j < POOL; j++) { s0[j] = 0.f; s1[j] = 0.f; }
        float ss0 = 0.f, ss1 = 0.f;

        #pragma unroll
        for (int i = 0; i < NVEC; i++) {
            // streaming loads: evict-first, keep keys/prompts resident in L1
            const float4 xv0 = __ldcs(xr0 + lane + 32 * i);
            const float4 xv1 = __ldcs(xr1 + lane + 32 * i);
            ss0 += xv0.x * xv0.x + xv0.y * xv0.y + xv0.z * xv0.z + xv0.w * xv0.w;
            ss1 += xv1.x * xv1.x + xv1.y * xv1.y + xv1.z * xv1.z + xv1.w * xv1.w;
            #pragma unroll
            for (int j = 0; j < POOL; j++) {
                const float4 kv = __ldg(knv + j * (DIM / 4) + lane + 32 * i);
                s0[j] += xv0.x * kv.x + xv0.y * kv.y + xv0.z * kv.z + xv0.w * kv.w;
                s1[j] += xv1.x * kv.x + xv1.y * kv.y + xv1.z * kv.z + xv1.w * kv.w;
            }
        }

        // butterfly reduce all 42 accumulators
        #pragma unroll
        for (int off = 16; off; off >>= 1) {
            ss0 += __shfl_xor_sync(0xffffffffu, ss0, off);
            ss1 += __shfl_xor_sync(0xffffffffu, ss1, off);
            #pragma unroll
            for (int j = 0; j < POOL; j++) {
                s0[j] += __shfl_xor_sync(0xffffffffu, s0[j], off);
                s1[j] += __shfl_xor_sync(0xffffffffu, s1[j], off);
            }
        }

        const float inv0 = 1.f / fmaxf(sqrtf(ss0), 1e-12f);
        const float inv1 = 1.f / fmaxf(sqrtf(ss1), 1e-12f);
        #pragma unroll
        for (int j = 0; j < POOL; j++) { s0[j] *= inv0; s1[j] *= inv1; }

        // dist bookkeeping: pool-sums of sim rows 0..19
        if (lane == 0) {
            if (r0 < POOL) {
                float rs = 0.f;
                #pragma unroll
                for (int j = 0; j < POOL; j++) rs += s0[j];
                g_rowsum[r0] = rs;
            }
            if (r1 < POOL) {
                float rs = 0.f;
                #pragma unroll
                for (int j = 0; j < POOL; j++) rs += s1[j];
                g_rowsum[r1] = rs;
            }
        }

        // iterative top-9 (strict '>' => lower index wins ties, matches lax.top_k)
        int idx0[TOPK], idx1[TOPK];
        #pragma unroll
        for (int t = 0; t < TOPK; t++) {
            float best = -3.4e38f; int bj = 0;
            #pragma unroll
            for (int j = 0; j < POOL; j++)
                if (s0[j] > best) { best = s0[j]; bj = j; }
            idx0[t] = bj;
            #pragma unroll
            for (int j = 0; j < POOL; j++)
                if (j == bj) s0[j] = -3.4e38f;
        }
        #pragma unroll
        for (int t = 0; t < TOPK; t++) {
            float best = -3.4e38f; int bj = 0;
            #pragma unroll
            for (int j = 0; j < POOL; j++)
                if (s1[j] > best) { best = s1[j]; bj = j; }
            idx1[t] = bj;
            #pragma unroll
            for (int j = 0; j < POOL; j++)
                if (j == bj) s1[j] = -3.4e38f;
        }

        if (lane == 0) {
            #pragma unroll
            for (int t = 0; t < TOPK; t++) {
                atomicAdd(&s_count[idx0[t]], 1u);
                atomicAdd(&s_count[idx1[t]], 1u);
            }
        }

        // gather: 18 prompt-row copies, coalesced streaming stores
        const float4* __restrict__ pbase =
            (const float4*)(prompts + (size_t)(*layer) * POOL * DIM);
        float4* __restrict__ o0 = (float4*)out + (size_t)r0 * (TOPK * DIM / 4);
        float4* __restrict__ o1 = (float4*)out + (size_t)r1 * (TOPK * DIM / 4);
        #pragma unroll
        for (int t = 0; t < TOPK; t++) {
            const float4* pr0 = pbase + idx0[t] * (DIM / 4);
            const float4* pr1 = pbase + idx1[t] * (DIM / 4);
            #pragma unroll
            for (int i = 0; i < NVEC; i++) {
                __stcs(o0 + t * (DIM / 4) + lane + 32 * i, __ldg(pr0 + lane + 32 * i));
                __stcs(o1 + t * (DIM / 4) + lane + 32 * i, __ldg(pr1 + lane + 32 * i));
            }
        }
    }

    __syncthreads();
    if (threadIdx.x < POOL)
        atomicAdd(&g_count[threadIdx.x], s_count[threadIdx.x]);
}

// ---------------------------------------------------------------------------
// finalize: dist = 1 - sum_r count[r]*rowsum[r] / (B*TOPK*POOL)
// ---------------------------------------------------------------------------
__global__ void finalize_kernel(float* __restrict__ out,
                                long long total, long long out_size, int B)
{
    double s = 0.0;
    #pragma unroll
    for (int r = 0; r < POOL; r++)
        s += (double)g_count[r] * (double)g_rowsum[r];
    const float dist = (float)(1.0 - s / ((double)B * TOPK * POOL));
    for (long long i = total + threadIdx.x; i < out_size; i += blockDim.x)
        out[i] = dist;
}

extern "C" void kernel_launch(void* const* d_in, const int* in_sizes, int n_in,
                              void* d_out, int out_size)
{
    const float* x       = (const float*)d_in[0];
    const float* keys    = (const float*)d_in[1];
    const float* prompts = (const float*)d_in[2];
    const int*   layer   = (const int*)d_in[3];

    const int B = in_sizes[0] / DIM;
    const long long total = (long long)B * TOPK * DIM;

    prep_kernel<<<1, 640>>>(keys, layer);
    pool_main<<<(B + ROWS_PER_BLOCK - 1) / ROWS_PER_BLOCK, 256>>>(
        x, prompts, layer, (float*)d_out, B);
    finalize_kernel<<<1, 32>>>((float*)d_out, total, (long long)out_size, B);
}

// round 15
// speedup vs baseline: 1.0653x; 1.0653x over previous
#include <cuda_runtime.h>

#define DIM   768
#define POOL  20
#define TOPK  9
#define NVEC  6                 // float4 chunks per lane: 768 / 4 / 32
#define WARPS 8
#define ROWS_PER_WARP  2
#define ROWS_PER_BLOCK (WARPS * ROWS_PER_WARP)   // 16

// Allocation-free scratch
__device__ float        g_kn[POOL * DIM];
__device__ float        g_rowsum[POOL];
__device__ unsigned int g_count[POOL];
__device__ unsigned int g_done = 0;

// ---------------------------------------------------------------------------
// prep: 1 block x 640 threads. Warp w normalizes key row w (shuffle-only).
// Re-zeros accumulators every replay (graph determinism).
// ---------------------------------------------------------------------------
__global__ void prep_kernel(const float* __restrict__ keys,
                            const int*   __restrict__ layer)
{
    const int w    = threadIdx.x >> 5;
    const int lane = threadIdx.x & 31;

    if (w < POOL) {
        const float* __restrict__ krow =
            keys + ((size_t)(*layer) * POOL + w) * DIM;
        float ss = 0.f;
        #pragma unroll
        for (int i = 0; i < DIM / 32; i++) {
            float v = __ldg(krow + lane + 32 * i);
            ss += v * v;
        }
        #pragma unroll
        for (int off = 16; off; off >>= 1)
            ss += __shfl_xor_sync(0xffffffffu, ss, off);
        const float inv = 1.f / fmaxf(sqrtf(ss), 1e-12f);
        #pragma unroll
        for (int i = 0; i < DIM / 32; i++)
            g_kn[w * DIM + lane + 32 * i] = __ldg(krow + lane + 32 * i) * inv;
    }
    if (threadIdx.x < POOL) {
        g_count[threadIdx.x]  = 0u;
        g_rowsum[threadIdx.x] = 0.f;
    }
}

// ---------------------------------------------------------------------------
// main: one warp handles TWO batch rows, 85-reg cap (3 CTAs/SM, 24 warps) —
// the R12 winner — plus a last-block finalize ticket replacing the third
// kernel launch. The cap keeps the cold epilogue from inflating the hot loop.
// ---------------------------------------------------------------------------
__global__ void __launch_bounds__(256, 3)
pool_main(const float* __restrict__ x,
          const float* __restrict__ prompts,
          const int*   __restrict__ layer,
          float*       __restrict__ out,
          int B, long long total, long long out_sz)
{
    __shared__ unsigned int s_count[POOL];
    __shared__ unsigned int s_last;
    if (threadIdx.x < POOL) s_count[threadIdx.x] = 0u;
    __syncthreads();

    const int warp = threadIdx.x >> 5;
    const int lane = threadIdx.x & 31;
    const int r0   = blockIdx.x * ROWS_PER_BLOCK + warp * ROWS_PER_WARP;
    const int r1   = r0 + 1;

    if (r1 < B) {
        const float4* __restrict__ xr0 = (const float4*)(x + (size_t)r0 * DIM);
        const float4* __restrict__ xr1 = (const float4*)(x + (size_t)r1 * DIM);
        const float4* __restrict__ knv = (const float4*)g_kn;

        float s0[POOL], s1[POOL];
        #pragma unroll
        for (int j = 0; j < POOL; j++) { s0[j] = 0.f; s1[j] = 0.f; }
        float ss0 = 0.f, ss1 = 0.f;

        #pragma unroll
        for (int i = 0; i < NVEC; i++) {
            // streaming loads: evict-first, keep keys/prompts resident in L1
            const float4 xv0 = __ldcs(xr0 + lane + 32 * i);
            const float4 xv1 = __ldcs(xr1 + lane + 32 * i);
            ss0 += xv0.x * xv0.x + xv0.y * xv0.y + xv0.z * xv0.z + xv0.w * xv0.w;
            ss1 += xv1.x * xv1.x + xv1.y * xv1.y + xv1.z * xv1.z + xv1.w * xv1.w;
            #pragma unroll
            for (int j = 0; j < POOL; j++) {
                const float4 kv = __ldg(knv + j * (DIM / 4) + lane + 32 * i);
                s0[j] += xv0.x * kv.x + xv0.y * kv.y + xv0.z * kv.z + xv0.w * kv.w;
                s1[j] += xv1.x * kv.x + xv1.y * kv.y + xv1.z * kv.z + xv1.w * kv.w;
            }
        }

        // butterfly reduce all 42 accumulators
        #pragma unroll
        for (int off = 16; off; off >>= 1) {
            ss0 += __shfl_xor_sync(0xffffffffu, ss0, off);
            ss1 += __shfl_xor_sync(0xffffffffu, ss1, off);
            #pragma unroll
            for (int j = 0; j < POOL; j++) {
                s0[j] += __shfl_xor_sync(0xffffffffu, s0[j], off);
                s1[j] += __shfl_xor_sync(0xffffffffu, s1[j], off);
            }
        }

        const float inv0 = 1.f / fmaxf(sqrtf(ss0), 1e-12f);
        const float inv1 = 1.f / fmaxf(sqrtf(ss1), 1e-12f);
        #pragma unroll
        for (int j = 0; j < POOL; j++) { s0[j] *= inv0; s1[j] *= inv1; }

        // dist bookkeeping: pool-sums of sim rows 0..19
        if (lane == 0) {
            if (r0 < POOL) {
                float rs = 0.f;
                #pragma unroll
                for (int j = 0; j < POOL; j++) rs += s0[j];
                g_rowsum[r0] = rs;
            }
            if (r1 < POOL) {
                float rs = 0.f;
                #pragma unroll
                for (int j = 0; j < POOL; j++) rs += s1[j];
                g_rowsum[r1] = rs;
            }
        }

        // iterative top-9 (strict '>' => lower index wins ties, matches lax.top_k)
        int idx0[TOPK], idx1[TOPK];
        #pragma unroll
        for (int t = 0; t < TOPK; t++) {
            float best = -3.4e38f; int bj = 0;
            #pragma unroll
            for (int j = 0; j < POOL; j++)
                if (s0[j] > best) { best = s0[j]; bj = j; }
            idx0[t] = bj;
            #pragma unroll
            for (int j = 0; j < POOL; j++)
                if (j == bj) s0[j] = -3.4e38f;
        }
        #pragma unroll
        for (int t = 0; t < TOPK; t++) {
            float best = -3.4e38f; int bj = 0;
            #pragma unroll
            for (int j = 0; j < POOL; j++)
                if (s1[j] > best) { best = s1[j]; bj = j; }
            idx1[t] = bj;
            #pragma unroll
            for (int j = 0; j < POOL; j++)
                if (j == bj) s1[j] = -3.4e38f;
        }

        if (lane == 0) {
            #pragma unroll
            for (int t = 0; t < TOPK; t++) {
                atomicAdd(&s_count[idx0[t]], 1u);
                atomicAdd(&s_count[idx1[t]], 1u);
            }
        }

        // gather: 18 prompt-row copies, coalesced streaming stores
        const float4* __restrict__ pbase =
            (const float4*)(prompts + (size_t)(*layer) * POOL * DIM);
        float4* __restrict__ o0 = (float4*)out + (size_t)r0 * (TOPK * DIM / 4);
        float4* __restrict__ o1 = (float4*)out + (size_t)r1 * (TOPK * DIM / 4);
        #pragma unroll
        for (int t = 0; t < TOPK; t++) {
            const float4* pr0 = pbase + idx0[t] * (DIM / 4);
            const float4* pr1 = pbase + idx1[t] * (DIM / 4);
            #pragma unroll
            for (int i = 0; i < NVEC; i++) {
                __stcs(o0 + t * (DIM / 4) + lane + 32 * i, __ldg(pr0 + lane + 32 * i));
                __stcs(o1 + t * (DIM / 4) + lane + 32 * i, __ldg(pr1 + lane + 32 * i));
            }
        }
    }

    __syncthreads();
    if (threadIdx.x < POOL)
        atomicAdd(&g_count[threadIdx.x], s_count[threadIdx.x]);

    // last-block finalize: dist = 1 - sum_r count[r]*rowsum[r] / (B*9*20)
    __threadfence();
    if (threadIdx.x == 0)
        s_last = (atomicAdd(&g_done, 1u) == gridDim.x - 1) ? 1u : 0u;
    __syncthreads();
    if (s_last && threadIdx.x == 0) {
        double acc = 0.0;
        #pragma unroll
        for (int r = 0; r < POOL; r++)
            acc += (double)g_count[r] * (double)g_rowsum[r];
        const float dist = (float)(1.0 - acc / ((double)B * TOPK * POOL));
        for (long long i = total; i < out_sz; i++) out[i] = dist;
        g_done = 0;   // reset for next graph replay (prep re-zeros the rest)
    }
}

extern "C" void kernel_launch(void* const* d_in, const int* in_sizes, int n_in,
                              void* d_out, int out_size)
{
    const float* x       = (const float*)d_in[0];
    const float* keys    = (const float*)d_in[1];
    const float* prompts = (const float*)d_in[2];
    const int*   layer   = (const int*)d_in[3];

    const int B = in_sizes[0] / DIM;
    const long long total = (long long)B * TOPK * DIM;

    prep_kernel<<<1, 640>>>(keys, layer);
    pool_main<<<(B + ROWS_PER_BLOCK - 1) / ROWS_PER_BLOCK, 256>>>(
        x, prompts, layer, (float*)d_out, B, total, (long long)out_size);
}

// round 16
// speedup vs baseline: 1.1277x; 1.0586x over previous
#include <cuda_runtime.h>

#define DIM   768
#define POOL  20
#define TOPK  9
#define NVEC  6                 // float4 chunks per lane: 768 / 4 / 32
#define WARPS 8
#define ROWS_PER_BLOCK WARPS    // 8: one row per warp

// Allocation-free scratch
__device__ float        g_kn[POOL * DIM];
__device__ float        g_rowsum[POOL];
__device__ unsigned int g_count[POOL];

// ---------------------------------------------------------------------------
// prep: 1 block x 640 threads. Warp w normalizes key row w (shuffle-only).
// Re-zeros accumulators every replay (graph determinism).
// ---------------------------------------------------------------------------
__global__ void prep_kernel(const float* __restrict__ keys,
                            const int*   __restrict__ layer)
{
    const int w    = threadIdx.x >> 5;
    const int lane = threadIdx.x & 31;

    if (w < POOL) {
        const float* __restrict__ krow =
            keys + ((size_t)(*layer) * POOL + w) * DIM;
        float ss = 0.f;
        #pragma unroll
        for (int i = 0; i < DIM / 32; i++) {
            float v = __ldg(krow + lane + 32 * i);
            ss += v * v;
        }
        #pragma unroll
        for (int off = 16; off; off >>= 1)
            ss += __shfl_xor_sync(0xffffffffu, ss, off);
        const float inv = 1.f / fmaxf(sqrtf(ss), 1e-12f);
        #pragma unroll
        for (int i = 0; i < DIM / 32; i++)
            g_kn[w * DIM + lane + 32 * i] = __ldg(krow + lane + 32 * i) * inv;
    }
    if (threadIdx.x < POOL) {
        g_count[threadIdx.x]  = 0u;
        g_rowsum[threadIdx.x] = 0.f;
    }
}

// ---------------------------------------------------------------------------
// main: ONE row per warp, 51-reg cap -> 5 CTAs/SM (40 warps). Small live set
// (20 sims + |x|^2 + one float4 of x) keeps it spill-free at high occupancy.
// ---------------------------------------------------------------------------
__global__ void __launch_bounds__(256, 5)
pool_main(const float* __restrict__ x,
          const float* __restrict__ prompts,
          const int*   __restrict__ layer,
          float*       __restrict__ out,
          int B)
{
    __shared__ unsigned int s_count[POOL];
    if (threadIdx.x < POOL) s_count[threadIdx.x] = 0u;
    __syncthreads();

    const int warp = threadIdx.x >> 5;
    const int lane = threadIdx.x & 31;
    const int row  = blockIdx.x * ROWS_PER_BLOCK + warp;

    if (row < B) {
        const float4* __restrict__ xr  = (const float4*)(x + (size_t)row * DIM);
        const float4* __restrict__ knv = (const float4*)g_kn;

        float s[POOL];
        #pragma unroll
        for (int j = 0; j < POOL; j++) s[j] = 0.f;
        float ss = 0.f;

        #pragma unroll
        for (int i = 0; i < NVEC; i++) {
            // streaming load: evict-first, keep keys/prompts resident in L1
            const float4 xv = __ldcs(xr + lane + 32 * i);
            ss += xv.x * xv.x + xv.y * xv.y + xv.z * xv.z + xv.w * xv.w;
            #pragma unroll
            for (int j = 0; j < POOL; j++) {
                const float4 kv = __ldg(knv + j * (DIM / 4) + lane + 32 * i);
                s[j] += xv.x * kv.x + xv.y * kv.y + xv.z * kv.z + xv.w * kv.w;
            }
        }

        // butterfly reduce 21 accumulators
        #pragma unroll
        for (int off = 16; off; off >>= 1) {
            ss += __shfl_xor_sync(0xffffffffu, ss, off);
            #pragma unroll
            for (int j = 0; j < POOL; j++)
                s[j] += __shfl_xor_sync(0xffffffffu, s[j], off);
        }

        const float inv = 1.f / fmaxf(sqrtf(ss), 1e-12f);
        #pragma unroll
        for (int j = 0; j < POOL; j++) s[j] *= inv;

        // dist bookkeeping: pool-sum of sim rows 0..19
        if (lane == 0 && row < POOL) {
            float rs = 0.f;
            #pragma unroll
            for (int j = 0; j < POOL; j++) rs += s[j];
            g_rowsum[row] = rs;
        }

        // iterative top-9 (strict '>' => lower index wins ties, matches lax.top_k)
        int idx[TOPK];
        #pragma unroll
        for (int t = 0; t < TOPK; t++) {
            float best = -3.4e38f; int bj = 0;
            #pragma unroll
            for (int j = 0; j < POOL; j++)
                if (s[j] > best) { best = s[j]; bj = j; }
            idx[t] = bj;
            #pragma unroll
            for (int j = 0; j < POOL; j++)
                if (j == bj) s[j] = -3.4e38f;
        }

        if (lane == 0) {
            #pragma unroll
            for (int t = 0; t < TOPK; t++)
                atomicAdd(&s_count[idx[t]], 1u);
        }

        // gather: 9 prompt-row copies, coalesced streaming stores
        const float4* __restrict__ pbase =
            (const float4*)(prompts + (size_t)(*layer) * POOL * DIM);
        float4* __restrict__ orow = (float4*)out + (size_t)row * (TOPK * DIM / 4);
        #pragma unroll
        for (int t = 0; t < TOPK; t++) {
            const float4* pr = pbase + idx[t] * (DIM / 4);
            #pragma unroll
            for (int i = 0; i < NVEC; i++)
                __stcs(orow + t * (DIM / 4) + lane + 32 * i,
                       __ldg(pr + lane + 32 * i));
        }
    }

    __syncthreads();
    if (threadIdx.x < POOL)
        atomicAdd(&g_count[threadIdx.x], s_count[threadIdx.x]);
}

// ---------------------------------------------------------------------------
// finalize: dist = 1 - sum_r count[r]*rowsum[r] / (B*TOPK*POOL)
// ---------------------------------------------------------------------------
__global__ void finalize_kernel(float* __restrict__ out,
                                long long total, long long out_size, int B)
{
    double s = 0.0;
    #pragma unroll
    for (int r = 0; r < POOL; r++)
        s += (double)g_count[r] * (double)g_rowsum[r];
    const float dist = (float)(1.0 - s / ((double)B * TOPK * POOL));
    for (long long i = total + threadIdx.x; i < out_size; i += blockDim.x)
        out[i] = dist;
}

extern "C" void kernel_launch(void* const* d_in, const int* in_sizes, int n_in,
                              void* d_out, int out_size)
{
    const float* x       = (const float*)d_in[0];
    const float* keys    = (const float*)d_in[1];
    const float* prompts = (const float*)d_in[2];
    const int*   layer   = (const int*)d_in[3];

    const int B = in_sizes[0] / DIM;
    const long long total = (long long)B * TOPK * DIM;

    prep_kernel<<<1, 640>>>(keys, layer);
    pool_main<<<(B + ROWS_PER_BLOCK - 1) / ROWS_PER_BLOCK, 256>>>(
        x, prompts, layer, (float*)d_out, B);
    finalize_kernel<<<1, 32>>>((float*)d_out, total, (long long)out_size, B);
}